// round 2
// baseline (speedup 1.0000x reference)
#include <cuda_runtime.h>
#include <cuda_bf16.h>
#include <cstdint>

// Problem constants
#define DIMD 512
#define KCB  1024
#define TT   2048
#define BBATCH 16
#define NROWS (BBATCH * TT)          // 32768
#define TOTAL (BBATCH * DIMD * TT)   // 16777216

// Scratch (no cudaMalloc allowed)
__device__ float  g_wsq[KCB];
__device__ float  g_zsq[NROWS];
__device__ int    g_idx[NROWS];
__device__ double g_loss_acc;

// ---------------------------------------------------------------------------
// Zero the loss accumulator (fresh every launch -> deterministic)
// ---------------------------------------------------------------------------
__global__ void vq_init_kernel() { g_loss_acc = 0.0; }

// ---------------------------------------------------------------------------
// z_sq[n] = sum_d z[b,d,t]^2, n = b*T + t.
// EXACT emulation of hypothesized XLA-CPU order: scalar sequential over d,
// UNFUSED mul then add (separate roundings) -> __fmul_rn / __fadd_rn.
// One thread per row; adjacent threads share t -> coalesced strided loads.
// ---------------------------------------------------------------------------
__global__ __launch_bounds__(256)
void vq_zsq_kernel(const float* __restrict__ z) {
    int n = blockIdx.x * blockDim.x + threadIdx.x;
    if (n >= NROWS) return;
    int b = n >> 11;
    int t = n & (TT - 1);
    const float* p = z + ((size_t)b << 20) + t;
    float s = 0.f;
    #pragma unroll 8
    for (int d = 0; d < DIMD; ++d) {
        float v = p[(size_t)d * TT];
        s = __fadd_rn(s, __fmul_rn(v, v));
    }
    g_zsq[n] = s;
}

// ---------------------------------------------------------------------------
// w_sq[k] = sum_d codebook[k][d]^2, scalar sequential, unfused mul/add.
// (Absolute error here is ~1e-11 regardless of order; sequential for safety.)
// ---------------------------------------------------------------------------
__global__ __launch_bounds__(256)
void vq_wsq_kernel(const float* __restrict__ cb) {
    int k = blockIdx.x * blockDim.x + threadIdx.x;
    if (k >= KCB) return;
    const float* row = cb + (size_t)k * DIMD;
    float s = 0.f;
    #pragma unroll 8
    for (int d = 0; d < DIMD; ++d)
        s = __fadd_rn(s, __fmul_rn(row[d], row[d]));
    g_wsq[k] = s;
}

// ---------------------------------------------------------------------------
// Main fused GEMM + argmin.
// CTA = 256 threads (16x16), tile = 64 rows x 64 cols, thread tile 4x4.
// Each accumulator is a single serial __fmaf_rn chain over d = 0..511 in
// ascending order -> bitwise identical to Eigen gebp's sequential fused-FMA
// depth loop (the XLA CPU f32 GEMM micro-kernel).
// Distance combine replicates the reference's rounding sequence exactly:
//   t    = fl32(z_sq - fl32(2*dot))
//   dist = fl32(t + w_sq)
// Argmin with lowest-index tie-break (== jnp.argmin).
// ---------------------------------------------------------------------------
__global__ __launch_bounds__(256)
void vq_argmin_kernel(const float* __restrict__ z,
                      const float* __restrict__ cb,
                      float* __restrict__ out_idx_f) {
    __shared__ float zs[16][68];   // transposed tiles, 272B pitch (16B aligned)
    __shared__ float ws[16][68];
    __shared__ float wsq_s[64];

    const int tid = threadIdx.x;
    const int tx  = tid & 15;   // col group
    const int ty  = tid >> 4;   // row group

    const int rb = blockIdx.x * 64;        // first flat row n of this CTA
    const int b  = rb >> 11;               // 64 | 2048 -> uniform per CTA
    const int t0 = rb & (TT - 1);
    const float* zbase = z + ((size_t)b * DIMD) * TT + t0;

    // z_sq for this thread's 4 rows
    float zsq_r[4];
    #pragma unroll
    for (int i = 0; i < 4; ++i) zsq_r[i] = g_zsq[rb + ty * 4 + i];

    float bestV[4] = {1e30f, 1e30f, 1e30f, 1e30f};
    int   bestI[4] = {0, 0, 0, 0};

    for (int kt = 0; kt < KCB / 64; ++kt) {
        const int k0 = kt * 64;
        if (tid < 64) wsq_s[tid] = g_wsq[k0 + tid];

        float acc[4][4];
        #pragma unroll
        for (int i = 0; i < 4; ++i)
            #pragma unroll
            for (int j = 0; j < 4; ++j) acc[i][j] = 0.f;

        for (int dt = 0; dt < DIMD / 16; ++dt) {
            const int d0 = dt * 16;
            // z tile: z[(b, d0+d, t0+r)] -> zs[d][r]  (coalesced 64-float rows)
            #pragma unroll
            for (int m = 0; m < 4; ++m) {
                int e = tid + m * 256;
                int d = e >> 6, r = e & 63;
                zs[d][r] = zbase[(size_t)(d0 + d) * TT + r];
            }
            // codebook tile transposed: cb[k0+k][d0+dc*4..+3] -> ws[d][k]
            {
                int k = tid >> 2, dc = tid & 3;
                float4 v = *(const float4*)(cb + (size_t)(k0 + k) * DIMD + d0 + dc * 4);
                ws[dc * 4 + 0][k] = v.x;
                ws[dc * 4 + 1][k] = v.y;
                ws[dc * 4 + 2][k] = v.z;
                ws[dc * 4 + 3][k] = v.w;
            }
            __syncthreads();
            #pragma unroll
            for (int dd = 0; dd < 16; ++dd) {
                float4 a  = *(const float4*)&zs[dd][ty * 4];
                float4 bb = *(const float4*)&ws[dd][tx * 4];
                acc[0][0] = __fmaf_rn(a.x, bb.x, acc[0][0]);
                acc[0][1] = __fmaf_rn(a.x, bb.y, acc[0][1]);
                acc[0][2] = __fmaf_rn(a.x, bb.z, acc[0][2]);
                acc[0][3] = __fmaf_rn(a.x, bb.w, acc[0][3]);
                acc[1][0] = __fmaf_rn(a.y, bb.x, acc[1][0]);
                acc[1][1] = __fmaf_rn(a.y, bb.y, acc[1][1]);
                acc[1][2] = __fmaf_rn(a.y, bb.z, acc[1][2]);
                acc[1][3] = __fmaf_rn(a.y, bb.w, acc[1][3]);
                acc[2][0] = __fmaf_rn(a.z, bb.x, acc[2][0]);
                acc[2][1] = __fmaf_rn(a.z, bb.y, acc[2][1]);
                acc[2][2] = __fmaf_rn(a.z, bb.z, acc[2][2]);
                acc[2][3] = __fmaf_rn(a.z, bb.w, acc[2][3]);
                acc[3][0] = __fmaf_rn(a.w, bb.x, acc[3][0]);
                acc[3][1] = __fmaf_rn(a.w, bb.y, acc[3][1]);
                acc[3][2] = __fmaf_rn(a.w, bb.z, acc[3][2]);
                acc[3][3] = __fmaf_rn(a.w, bb.w, acc[3][3]);
            }
            __syncthreads();
        }

        // dist = fl(fl(z_sq - 2*dot) + w_sq); per-row argmin (ties -> lowest k)
        #pragma unroll
        for (int i = 0; i < 4; ++i) {
            float v;
            int   idx;
            #pragma unroll
            for (int j = 0; j < 4; ++j) {
                float t  = __fsub_rn(zsq_r[i], __fmul_rn(2.0f, acc[i][j]));
                float vj = __fadd_rn(t, wsq_s[tx * 4 + j]);
                if (j == 0 || vj < v) {
                    if (j == 0) { v = vj; idx = k0 + tx * 4; }
                    else        { v = vj; idx = k0 + tx * 4 + j; }
                }
            }
            // butterfly min over the 16 column-group lanes (stays in half-warp)
            #pragma unroll
            for (int off = 1; off < 16; off <<= 1) {
                float ov = __shfl_xor_sync(0xffffffffu, v, off);
                int   oi = __shfl_xor_sync(0xffffffffu, idx, off);
                if (ov < v || (ov == v && oi < idx)) { v = ov; idx = oi; }
            }
            if (v < bestV[i]) { bestV[i] = v; bestI[i] = idx; }
        }
        __syncthreads();   // protect wsq_s before next k-tile overwrites it
    }

    if (tx == 0) {
        #pragma unroll
        for (int i = 0; i < 4; ++i) {
            int n = rb + ty * 4 + i;
            g_idx[n]     = bestI[i];
            out_idx_f[n] = (float)bestI[i];
        }
    }
}

// ---------------------------------------------------------------------------
// Gather z_q, write z_q_st = z + (z_q - z), accumulate sum((z_q - z)^2)
// ---------------------------------------------------------------------------
__global__ __launch_bounds__(256)
void vq_gather_kernel(const float* __restrict__ z,
                      const float* __restrict__ cb,
                      float* __restrict__ out) {
    float ls = 0.f;
    const int stride = gridDim.x * blockDim.x;
    for (int o = blockIdx.x * blockDim.x + threadIdx.x; o < TOTAL; o += stride) {
        int t = o & (TT - 1);
        int d = (o >> 11) & (DIMD - 1);
        int b = o >> 20;
        int n = (b << 11) + t;
        int idx = g_idx[n];
        float w  = __ldg(cb + (size_t)idx * DIMD + d);   // L2-resident gather
        float zv = z[o];
        float diff = __fsub_rn(w, zv);                   // z_q - z (ref order)
        out[o] = __fadd_rn(zv, diff);                    // straight-through
        ls += diff * diff;
    }
    double dl = (double)ls;
    #pragma unroll
    for (int off = 16; off; off >>= 1)
        dl += __shfl_xor_sync(0xffffffffu, dl, off);
    if ((threadIdx.x & 31) == 0) atomicAdd(&g_loss_acc, dl);
}

__global__ void vq_finalize_kernel(float* __restrict__ out_loss) {
    double mse = g_loss_acc / (double)TOTAL;
    float m = (float)mse;
    *out_loss = m + 0.25f * m;   // commitment + BETA * codebook
}

// ---------------------------------------------------------------------------
extern "C" void kernel_launch(void* const* d_in, const int* in_sizes, int n_in,
                              void* d_out, int out_size) {
    const float* z  = (const float*)d_in[0];
    const float* cb = (const float*)d_in[1];
    float* out       = (float*)d_out;
    float* out_idx_f = out + TOTAL;            // indices region (as float)
    float* out_loss  = out_idx_f + NROWS;      // scalar loss

    vq_init_kernel<<<1, 1>>>();
    vq_zsq_kernel<<<NROWS / 256, 256>>>(z);
    vq_wsq_kernel<<<KCB / 256, 256>>>(cb);
    vq_argmin_kernel<<<NROWS / 64, 256>>>(z, cb, out_idx_f);
    vq_gather_kernel<<<4096, 256>>>(z, cb, out);
    vq_finalize_kernel<<<1, 1>>>(out_loss);
}